// round 2
// baseline (speedup 1.0000x reference)
#include <cuda_runtime.h>
#include <math.h>

#define D_MODEL 1024
#define S_LEN   2048
#define BATCH   2
#define N_HEADS 16
#define HDIM    64
#define M_TOTAL (BATCH * S_LEN)   // 4096

// ---------------- scratch (device globals; no allocation allowed) ----------
__device__ float g_q[(size_t)M_TOTAL * D_MODEL];
__device__ float g_k[(size_t)M_TOTAL * D_MODEL];
__device__ float g_v[(size_t)M_TOTAL * D_MODEL];
__device__ float g_ctx[(size_t)M_TOTAL * D_MODEL];

// ---------------- GEMM: C[M,N] = A[M,K] @ W[K,N] + bias ----------------
// M=4096, N=1024, K=1024. BM=BN=128, BK=8, 256 threads, 8x8 per thread.
#define GBM 128
#define GBN 128
#define GBK 8

__global__ __launch_bounds__(256, 2)
void gemm_bias_kernel(const float* __restrict__ A, const float* __restrict__ W,
                      const float* __restrict__ bias, float* __restrict__ C)
{
    const int M = M_TOTAL, N = D_MODEL, K = D_MODEL;
    __shared__ float As[GBK][GBM + 4];   // [k][row], padded (conflict-free scatter)
    __shared__ float Ws[GBK][GBN];       // [k][col]

    const int tid = threadIdx.x;
    const int ty = tid >> 4;      // 0..15
    const int tx = tid & 15;      // 0..15
    const int m0 = blockIdx.y * GBM;
    const int n0 = blockIdx.x * GBN;

    // A loads: row = tid/2, 4 cols at (tid&1)*4
    const int arow = tid >> 1;
    const int acol = (tid & 1) * 4;
    // W loads: row = tid/32, 4 cols at (tid&31)*4
    const int wrow = tid >> 5;
    const int wcol = (tid & 31) * 4;

    const float* Aptr = A + (size_t)(m0 + arow) * K + acol;
    const float* Wptr = W + (size_t)wrow * N + n0 + wcol;

    float acc[8][8];
    #pragma unroll
    for (int i = 0; i < 8; i++)
        #pragma unroll
        for (int j = 0; j < 8; j++) acc[i][j] = 0.0f;

    for (int k0 = 0; k0 < K; k0 += GBK) {
        float4 av = *(const float4*)(Aptr + k0);
        float4 wv = *(const float4*)(Wptr + (size_t)k0 * N);
        As[acol + 0][arow] = av.x;
        As[acol + 1][arow] = av.y;
        As[acol + 2][arow] = av.z;
        As[acol + 3][arow] = av.w;
        *(float4*)&Ws[wrow][wcol] = wv;
        __syncthreads();

        #pragma unroll
        for (int k = 0; k < GBK; k++) {
            float4 a0 = *(const float4*)&As[k][ty * 4];
            float4 a1 = *(const float4*)&As[k][ty * 4 + 64];
            float4 b0 = *(const float4*)&Ws[k][tx * 4];
            float4 b1 = *(const float4*)&Ws[k][tx * 4 + 64];
            float ar[8] = {a0.x, a0.y, a0.z, a0.w, a1.x, a1.y, a1.z, a1.w};
            float br[8] = {b0.x, b0.y, b0.z, b0.w, b1.x, b1.y, b1.z, b1.w};
            #pragma unroll
            for (int i = 0; i < 8; i++)
                #pragma unroll
                for (int j = 0; j < 8; j++)
                    acc[i][j] = fmaf(ar[i], br[j], acc[i][j]);
        }
        __syncthreads();
    }

    float4 bb0 = *(const float4*)(bias + n0 + tx * 4);
    float4 bb1 = *(const float4*)(bias + n0 + tx * 4 + 64);

    #pragma unroll
    for (int i = 0; i < 8; i++) {
        int row = m0 + ((i < 4) ? (ty * 4 + i) : (ty * 4 + 64 + (i - 4)));
        float4 o0 = make_float4(acc[i][0] + bb0.x, acc[i][1] + bb0.y,
                                acc[i][2] + bb0.z, acc[i][3] + bb0.w);
        float4 o1 = make_float4(acc[i][4] + bb1.x, acc[i][5] + bb1.y,
                                acc[i][6] + bb1.z, acc[i][7] + bb1.w);
        *(float4*)(C + (size_t)row * N + n0 + tx * 4)      = o0;
        *(float4*)(C + (size_t)row * N + n0 + tx * 4 + 64) = o1;
    }
}

// ---------------- Flash attention: 64 queries x 64-key tiles, Dk=64 --------
// smem layout (dynamic): Qt[64][68] (d-major), Kt[64][68] (d-major),
//                        Vs[64][68] (key-major), Pt[64][68] (key-major, P^T)
#define APAD 68
#define ATTN_SMEM (4 * 64 * APAD * 4)

__global__ __launch_bounds__(256, 2)
void attn_kernel(const float* __restrict__ Q, const float* __restrict__ K,
                 const float* __restrict__ V, float* __restrict__ O)
{
    extern __shared__ float smem[];
    float* Qt = smem;                 // Qt[d*APAD + row], pre-scaled by 1/sqrt(dk)
    float* Kt = smem + 64 * APAD;     // Kt[d*APAD + key]
    float* Vs = smem + 2 * 64 * APAD; // Vs[key*APAD + d]
    float* Pt = smem + 3 * 64 * APAD; // Pt[key*APAD + row]

    const int qt = blockIdx.x;        // query tile (0..31)
    const int h  = blockIdx.y;        // head
    const int b  = blockIdx.z;        // batch
    const int tid = threadIdx.x;
    const int ty = tid >> 4;          // 0..15 -> query rows ty*4..ty*4+3
    const int tx = tid & 15;          // 0..15 -> cols tx*4..tx*4+3

    const int q0 = qt * 64;
    const size_t head_off = (size_t)h * HDIM;
    const size_t batch_off = (size_t)b * S_LEN * D_MODEL;

    // Load Q tile, pre-scaled, transposed into Qt[d][row]
    const float scale = 0.125f; // 1/sqrt(64)
    #pragma unroll
    for (int it = 0; it < 4; it++) {
        int idx = tid + it * 256;           // 0..1023 float4s
        int row = idx >> 4;                 // 0..63
        int c4  = (idx & 15) * 4;           // 0..60
        float4 qv = *(const float4*)(Q + batch_off + (size_t)(q0 + row) * D_MODEL + head_off + c4);
        Qt[(c4 + 0) * APAD + row] = qv.x * scale;
        Qt[(c4 + 1) * APAD + row] = qv.y * scale;
        Qt[(c4 + 2) * APAD + row] = qv.z * scale;
        Qt[(c4 + 3) * APAD + row] = qv.w * scale;
    }

    float o_acc[4][4];
    float m_run[4], l_run[4];
    #pragma unroll
    for (int r = 0; r < 4; r++) {
        m_run[r] = -1e30f;
        l_run[r] = 0.0f;
        #pragma unroll
        for (int c = 0; c < 4; c++) o_acc[r][c] = 0.0f;
    }

    for (int j = 0; j < S_LEN / 64; j++) {
        // Load K tile (transposed) and V tile (natural)
        const int k0 = j * 64;
        #pragma unroll
        for (int it = 0; it < 4; it++) {
            int idx = tid + it * 256;
            int row = idx >> 4;
            int c4  = (idx & 15) * 4;
            size_t goff = batch_off + (size_t)(k0 + row) * D_MODEL + head_off + c4;
            float4 kv = *(const float4*)(K + goff);
            Kt[(c4 + 0) * APAD + row] = kv.x;
            Kt[(c4 + 1) * APAD + row] = kv.y;
            Kt[(c4 + 2) * APAD + row] = kv.z;
            Kt[(c4 + 3) * APAD + row] = kv.w;
            float4 vv = *(const float4*)(V + goff);
            *(float4*)&Vs[row * APAD + c4] = vv;
        }
        __syncthreads();

        // Scores: s[r][c] = sum_d Qt[d][ty*4+r] * Kt[d][tx*4+c]
        float s[4][4];
        #pragma unroll
        for (int r = 0; r < 4; r++)
            #pragma unroll
            for (int c = 0; c < 4; c++) s[r][c] = 0.0f;

        #pragma unroll 8
        for (int d = 0; d < 64; d++) {
            float4 qa = *(const float4*)&Qt[d * APAD + ty * 4];
            float4 kb = *(const float4*)&Kt[d * APAD + tx * 4];
            float ar[4] = {qa.x, qa.y, qa.z, qa.w};
            float br[4] = {kb.x, kb.y, kb.z, kb.w};
            #pragma unroll
            for (int r = 0; r < 4; r++)
                #pragma unroll
                for (int c = 0; c < 4; c++)
                    s[r][c] = fmaf(ar[r], br[c], s[r][c]);
        }

        // Online softmax per query row (row owned by 16-lane group of same ty)
        #pragma unroll
        for (int r = 0; r < 4; r++) {
            float rm = fmaxf(fmaxf(s[r][0], s[r][1]), fmaxf(s[r][2], s[r][3]));
            #pragma unroll
            for (int off = 8; off >= 1; off >>= 1)
                rm = fmaxf(rm, __shfl_xor_sync(0xffffffffu, rm, off, 16));
            float mnew = fmaxf(m_run[r], rm);
            float corr = __expf(m_run[r] - mnew);
            float rs = 0.0f;
            #pragma unroll
            for (int c = 0; c < 4; c++) {
                s[r][c] = __expf(s[r][c] - mnew);
                rs += s[r][c];
            }
            #pragma unroll
            for (int off = 8; off >= 1; off >>= 1)
                rs += __shfl_xor_sync(0xffffffffu, rs, off, 16);
            l_run[r] = l_run[r] * corr + rs;
            m_run[r] = mnew;
            #pragma unroll
            for (int c = 0; c < 4; c++) o_acc[r][c] *= corr;
        }

        // Write P^T to smem: Pt[key][row]
        #pragma unroll
        for (int i = 0; i < 4; i++) {
            float4 pv = make_float4(s[0][i], s[1][i], s[2][i], s[3][i]);
            *(float4*)&Pt[(tx * 4 + i) * APAD + ty * 4] = pv;
        }
        __syncthreads();

        // PV: o[r][c] += sum_k Pt[k][ty*4+r] * Vs[k][tx*4+c]
        #pragma unroll 8
        for (int k = 0; k < 64; k++) {
            float4 pa = *(const float4*)&Pt[k * APAD + ty * 4];
            float4 vb = *(const float4*)&Vs[k * APAD + tx * 4];
            float pr[4] = {pa.x, pa.y, pa.z, pa.w};
            float vr[4] = {vb.x, vb.y, vb.z, vb.w};
            #pragma unroll
            for (int r = 0; r < 4; r++)
                #pragma unroll
                for (int c = 0; c < 4; c++)
                    o_acc[r][c] = fmaf(pr[r], vr[c], o_acc[r][c]);
        }
        __syncthreads();
    }

    // Epilogue: normalize and store to ctx [B,S,D_MODEL]
    #pragma unroll
    for (int r = 0; r < 4; r++) {
        float inv = 1.0f / l_run[r];
        float4 ov = make_float4(o_acc[r][0] * inv, o_acc[r][1] * inv,
                                o_acc[r][2] * inv, o_acc[r][3] * inv);
        *(float4*)(O + batch_off + (size_t)(q0 + ty * 4 + r) * D_MODEL + head_off + tx * 4) = ov;
    }
}

// ---------------- launch -------------------------------------------------
extern "C" void kernel_launch(void* const* d_in, const int* in_sizes, int n_in,
                              void* d_out, int out_size)
{
    const float* x  = (const float*)d_in[0];
    const float* Wq = (const float*)d_in[1];
    const float* bq = (const float*)d_in[2];
    const float* Wk = (const float*)d_in[3];
    const float* bk = (const float*)d_in[4];
    const float* Wv = (const float*)d_in[5];
    const float* bv = (const float*)d_in[6];
    const float* Wo = (const float*)d_in[7];
    const float* bo = (const float*)d_in[8];
    float* out = (float*)d_out;

    float *q, *k, *v, *ctx;
    cudaGetSymbolAddress((void**)&q,   g_q);
    cudaGetSymbolAddress((void**)&k,   g_k);
    cudaGetSymbolAddress((void**)&v,   g_v);
    cudaGetSymbolAddress((void**)&ctx, g_ctx);

    cudaFuncSetAttribute(attn_kernel, cudaFuncAttributeMaxDynamicSharedMemorySize, ATTN_SMEM);

    dim3 ggrid(D_MODEL / GBN, M_TOTAL / GBM);  // (8, 32)
    gemm_bias_kernel<<<ggrid, 256>>>(x, Wq, bq, q);
    gemm_bias_kernel<<<ggrid, 256>>>(x, Wk, bk, k);
    gemm_bias_kernel<<<ggrid, 256>>>(x, Wv, bv, v);

    dim3 agrid(S_LEN / 64, N_HEADS, BATCH);    // (32, 16, 2)
    attn_kernel<<<agrid, 256, ATTN_SMEM>>>(q, k, v, ctx);

    gemm_bias_kernel<<<ggrid, 256>>>(ctx, Wo, bo, out);
}

// round 7
// speedup vs baseline: 3.0621x; 3.0621x over previous
#include <cuda_runtime.h>
#include <cstdint>
#include <math.h>

#define D_MODEL 1024
#define S_LEN   2048
#define BATCH   2
#define N_HEADS 16
#define HDIM    64
#define M_TOTAL (BATCH * S_LEN)   // 4096

// ---------------- scratch (device globals; no allocation allowed) ----------
__device__ float g_q[(size_t)M_TOTAL * D_MODEL];
__device__ float g_k[(size_t)M_TOTAL * D_MODEL];
__device__ float g_v[(size_t)M_TOTAL * D_MODEL];
__device__ float g_ctx[(size_t)M_TOTAL * D_MODEL];
__device__ float g_wt[4][(size_t)D_MODEL * D_MODEL];   // transposed weights [N,K]

// ================= helpers ================================================
__device__ __forceinline__ float to_tf32(float x) {
    float r;
    asm("cvt.rna.tf32.f32 %0, %1;" : "=f"(r) : "f"(x));
    return r;
}
__device__ __forceinline__ uint32_t fau(float x) { return __float_as_uint(x); }

// D += A(16x8,row) * B(8x8,col)   tf32 -> f32
__device__ __forceinline__ void mma_tf32(float* d, const uint32_t* a, const uint32_t* b) {
    asm volatile(
        "mma.sync.aligned.m16n8k8.row.col.f32.tf32.tf32.f32 "
        "{%0,%1,%2,%3}, {%4,%5,%6,%7}, {%8,%9}, {%0,%1,%2,%3};"
        : "+f"(d[0]), "+f"(d[1]), "+f"(d[2]), "+f"(d[3])
        : "r"(a[0]), "r"(a[1]), "r"(a[2]), "r"(a[3]), "r"(b[0]), "r"(b[1]));
}

// ================= weight transpose: Wt[n*K+k] = W[k*N+n] ==================
__global__ __launch_bounds__(256)
void transpose_kernel(const float* __restrict__ in, float* __restrict__ out)
{
    __shared__ float t[32][33];
    const int bx = blockIdx.x * 32, by = blockIdx.y * 32;
    const int x = threadIdx.x & 31;
    const int y0 = (threadIdx.x >> 5) * 4;
    #pragma unroll
    for (int j = 0; j < 4; j++)
        t[y0 + j][x] = in[(size_t)(by + y0 + j) * D_MODEL + bx + x];
    __syncthreads();
    #pragma unroll
    for (int j = 0; j < 4; j++)
        out[(size_t)(bx + y0 + j) * D_MODEL + by + x] = t[x][y0 + j];
}

// ================= tf32 mma GEMM: C = A[M,K] @ Bt[N,K]^T + bias ============
// CTA 128x128, 8 warps (2m x 4n), warp tile 64x32, BK=32, double-buffered.
#define GSTR 36
#define GSTAGE (2 * 128 * GSTR)          // floats per stage (A + B)
#define GEMM_SMEM_BYTES (2 * GSTAGE * 4) // 73728

__global__ __launch_bounds__(256, 2)
void gemm_mma_kernel(const float* __restrict__ A, const float* __restrict__ Bt,
                     const float* __restrict__ bias, float* __restrict__ C)
{
    extern __shared__ float sm[];
    const int tid = threadIdx.x;
    const int lane = tid & 31;
    const int warp = tid >> 5;
    const int g = lane >> 2;          // 0..7
    const int t = lane & 3;           // 0..3
    const int wm = (warp & 1) * 64;
    const int wn = (warp >> 1) * 32;
    const int m0 = blockIdx.y * 128;
    const int n0 = blockIdx.x * 128;

    float acc[4][4][4];
    #pragma unroll
    for (int mf = 0; mf < 4; mf++)
        #pragma unroll
        for (int nf = 0; nf < 4; nf++)
            #pragma unroll
            for (int r = 0; r < 4; r++) acc[mf][nf][r] = 0.0f;

    // prologue: chunk 0 -> stage 0
    #pragma unroll
    for (int p = 0; p < 4; p++) {
        int idx = tid + p * 256;
        int r = idx >> 3, c = (idx & 7) * 4;
        float4 va = *(const float4*)(A  + (size_t)(m0 + r) * D_MODEL + c);
        float4 vb = *(const float4*)(Bt + (size_t)(n0 + r) * D_MODEL + c);
        va.x = to_tf32(va.x); va.y = to_tf32(va.y); va.z = to_tf32(va.z); va.w = to_tf32(va.w);
        vb.x = to_tf32(vb.x); vb.y = to_tf32(vb.y); vb.z = to_tf32(vb.z); vb.w = to_tf32(vb.w);
        *(float4*)(sm + r * GSTR + c) = va;
        *(float4*)(sm + 128 * GSTR + r * GSTR + c) = vb;
    }
    __syncthreads();

    for (int i = 0; i < 32; i++) {
        const int s = i & 1;
        float4 ra[4], rb[4];
        if (i + 1 < 32) {
            #pragma unroll
            for (int p = 0; p < 4; p++) {
                int idx = tid + p * 256;
                int r = idx >> 3, c = (idx & 7) * 4;
                ra[p] = *(const float4*)(A  + (size_t)(m0 + r) * D_MODEL + (i + 1) * 32 + c);
                rb[p] = *(const float4*)(Bt + (size_t)(n0 + r) * D_MODEL + (i + 1) * 32 + c);
            }
        }
        const float* As = sm + s * GSTAGE;
        const float* Bs = As + 128 * GSTR;

        #pragma unroll
        for (int ks = 0; ks < 4; ks++) {
            uint32_t bfr[4][2];
            #pragma unroll
            for (int nf = 0; nf < 4; nf++) {
                const float* bp = Bs + (wn + nf * 8 + g) * GSTR + ks * 8 + t;
                bfr[nf][0] = fau(bp[0]);
                bfr[nf][1] = fau(bp[4]);
            }
            #pragma unroll
            for (int mf = 0; mf < 4; mf++) {
                const float* ap = As + (wm + mf * 16 + g) * GSTR + ks * 8 + t;
                uint32_t afr[4];
                afr[0] = fau(ap[0]);
                afr[1] = fau(ap[8 * GSTR]);
                afr[2] = fau(ap[4]);
                afr[3] = fau(ap[8 * GSTR + 4]);
                #pragma unroll
                for (int nf = 0; nf < 4; nf++)
                    mma_tf32(acc[mf][nf], afr, bfr[nf]);
            }
        }

        if (i + 1 < 32) {
            float* nAs = sm + (s ^ 1) * GSTAGE;
            float* nBs = nAs + 128 * GSTR;
            #pragma unroll
            for (int p = 0; p < 4; p++) {
                int idx = tid + p * 256;
                int r = idx >> 3, c = (idx & 7) * 4;
                float4 va = ra[p], vb = rb[p];
                va.x = to_tf32(va.x); va.y = to_tf32(va.y); va.z = to_tf32(va.z); va.w = to_tf32(va.w);
                vb.x = to_tf32(vb.x); vb.y = to_tf32(vb.y); vb.z = to_tf32(vb.z); vb.w = to_tf32(vb.w);
                *(float4*)(nAs + r * GSTR + c) = va;
                *(float4*)(nBs + r * GSTR + c) = vb;
            }
        }
        __syncthreads();
    }

    // epilogue: C rows = m0+wm+mf*16+g(+8), cols = n0+wn+nf*8+2t(+1)
    #pragma unroll
    for (int mf = 0; mf < 4; mf++) {
        #pragma unroll
        for (int h = 0; h < 2; h++) {
            const int row = m0 + wm + mf * 16 + g + h * 8;
            float* crow = C + (size_t)row * D_MODEL + n0 + wn;
            #pragma unroll
            for (int nf = 0; nf < 4; nf++) {
                const int col = nf * 8 + 2 * t;
                float2 o;
                o.x = acc[mf][nf][2 * h]     + bias[n0 + wn + col];
                o.y = acc[mf][nf][2 * h + 1] + bias[n0 + wn + col + 1];
                *(float2*)(crow + col) = o;
            }
        }
    }
}

// ================= flash attention with tf32 mma ===========================
// CTA: 128 q-rows, 8 warps x 16 rows. 64-key tiles, dk=64.
#define AQ_STR 68
#define AV_STR 72
#define OFF_Q 0
#define OFF_K (128 * AQ_STR)
#define OFF_V (OFF_K + 64 * AQ_STR)
#define OFF_P (OFF_V + 64 * AV_STR)
#define ATTN_SMEM_BYTES ((OFF_P + 128 * AQ_STR) * 4)   // 105472

__global__ __launch_bounds__(256, 2)
void attn_mma_kernel(const float* __restrict__ Q, const float* __restrict__ K,
                     const float* __restrict__ V, float* __restrict__ Out)
{
    extern __shared__ float sm[];
    float* Qs = sm + OFF_Q;
    float* Ks = sm + OFF_K;
    float* Vs = sm + OFF_V;
    float* Ps = sm + OFF_P;

    const int tid = threadIdx.x;
    const int lane = tid & 31;
    const int warp = tid >> 5;
    const int g = lane >> 2;
    const int t = lane & 3;
    const int q0 = blockIdx.x * 128;
    const size_t hoff = (size_t)blockIdx.y * HDIM;
    const size_t boff = (size_t)blockIdx.z * S_LEN * D_MODEL;

    // fold 1/sqrt(dk) and log2(e) into Q: exp2 later computes exact softmax
    const float qscale = 0.125f * 1.4426950408889634f;
    #pragma unroll
    for (int p = 0; p < 8; p++) {
        int idx = tid + p * 256;
        int r = idx >> 4, c = (idx & 15) * 4;
        float4 v = *(const float4*)(Q + boff + (size_t)(q0 + r) * D_MODEL + hoff + c);
        v.x = to_tf32(v.x * qscale); v.y = to_tf32(v.y * qscale);
        v.z = to_tf32(v.z * qscale); v.w = to_tf32(v.w * qscale);
        *(float4*)(Qs + r * AQ_STR + c) = v;
    }

    float o[8][4];
    #pragma unroll
    for (int nf = 0; nf < 8; nf++)
        #pragma unroll
        for (int r = 0; r < 4; r++) o[nf][r] = 0.0f;
    float mrun[2] = {-1e30f, -1e30f};
    float lrun[2] = {0.0f, 0.0f};

    for (int kt = 0; kt < 32; kt++) {
        __syncthreads();   // prev iter's Vs/Ks reads done (also orders Qs on kt=0)
        #pragma unroll
        for (int p = 0; p < 4; p++) {
            int idx = tid + p * 256;
            int r = idx >> 4, c = (idx & 15) * 4;
            size_t go = boff + (size_t)(kt * 64 + r) * D_MODEL + hoff + c;
            float4 kv = *(const float4*)(K + go);
            kv.x = to_tf32(kv.x); kv.y = to_tf32(kv.y); kv.z = to_tf32(kv.z); kv.w = to_tf32(kv.w);
            *(float4*)(Ks + r * AQ_STR + c) = kv;
            float4 vv = *(const float4*)(V + go);
            vv.x = to_tf32(vv.x); vv.y = to_tf32(vv.y); vv.z = to_tf32(vv.z); vv.w = to_tf32(vv.w);
            *(float4*)(Vs + r * AV_STR + c) = vv;
        }
        __syncthreads();

        // S = Q * K^T  (warp rows: warp*16 + g, +8)
        float s[8][4];
        #pragma unroll
        for (int nf = 0; nf < 8; nf++)
            #pragma unroll
            for (int r = 0; r < 4; r++) s[nf][r] = 0.0f;

        #pragma unroll
        for (int ks = 0; ks < 8; ks++) {
            const float* ap = Qs + (warp * 16 + g) * AQ_STR + ks * 8 + t;
            uint32_t a[4];
            a[0] = fau(ap[0]);
            a[1] = fau(ap[8 * AQ_STR]);
            a[2] = fau(ap[4]);
            a[3] = fau(ap[8 * AQ_STR + 4]);
            #pragma unroll
            for (int nf = 0; nf < 8; nf++) {
                const float* bp = Ks + (nf * 8 + g) * AQ_STR + ks * 8 + t;
                uint32_t b[2] = {fau(bp[0]), fau(bp[4])};
                mma_tf32(s[nf], a, b);
            }
        }

        // online softmax, per row-half (rows g and g+8 of this warp)
        #pragma unroll
        for (int h = 0; h < 2; h++) {
            float mx = mrun[h];
            #pragma unroll
            for (int nf = 0; nf < 8; nf++)
                mx = fmaxf(mx, fmaxf(s[nf][2 * h], s[nf][2 * h + 1]));
            mx = fmaxf(mx, __shfl_xor_sync(0xffffffffu, mx, 1));
            mx = fmaxf(mx, __shfl_xor_sync(0xffffffffu, mx, 2));
            float corr = exp2f(mrun[h] - mx);
            float rs = 0.0f;
            float* prow = Ps + (warp * 16 + g + 8 * h) * AQ_STR + 2 * t;
            #pragma unroll
            for (int nf = 0; nf < 8; nf++) {
                float e0 = exp2f(s[nf][2 * h] - mx);
                float e1 = exp2f(s[nf][2 * h + 1] - mx);
                rs += e0 + e1;
                float2 pv = make_float2(to_tf32(e0), to_tf32(e1));
                *(float2*)(prow + nf * 8) = pv;
            }
            rs += __shfl_xor_sync(0xffffffffu, rs, 1);
            rs += __shfl_xor_sync(0xffffffffu, rs, 2);
            lrun[h] = lrun[h] * corr + rs;
            mrun[h] = mx;
            #pragma unroll
            for (int nf = 0; nf < 8; nf++) {
                o[nf][2 * h]     *= corr;
                o[nf][2 * h + 1] *= corr;
            }
        }
        __syncwarp();   // P stores visible to own warp's loads

        // O += P * V
        #pragma unroll
        for (int ks = 0; ks < 8; ks++) {
            const float* ap = Ps + (warp * 16 + g) * AQ_STR + ks * 8 + t;
            uint32_t a[4];
            a[0] = fau(ap[0]);
            a[1] = fau(ap[8 * AQ_STR]);
            a[2] = fau(ap[4]);
            a[3] = fau(ap[8 * AQ_STR + 4]);
            #pragma unroll
            for (int nf = 0; nf < 8; nf++) {
                const float* bp = Vs + (ks * 8 + t) * AV_STR + nf * 8 + g;
                uint32_t b[2] = {fau(bp[0]), fau(bp[4 * AV_STR])};
                mma_tf32(o[nf], a, b);
            }
        }
    }

    // epilogue: normalize, write ctx
    #pragma unroll
    for (int h = 0; h < 2; h++) {
        const int row = q0 + warp * 16 + g + 8 * h;
        const float inv = 1.0f / lrun[h];
        float* op = Out + boff + (size_t)row * D_MODEL + hoff;
        #pragma unroll
        for (int nf = 0; nf < 8; nf++) {
            float2 v = make_float2(o[nf][2 * h] * inv, o[nf][2 * h + 1] * inv);
            *(float2*)(op + nf * 8 + 2 * t) = v;
        }
    }
}

// ---------------- launch -------------------------------------------------
extern "C" void kernel_launch(void* const* d_in, const int* in_sizes, int n_in,
                              void* d_out, int out_size)
{
    const float* x  = (const float*)d_in[0];
    const float* Wq = (const float*)d_in[1];
    const float* bq = (const float*)d_in[2];
    const float* Wk = (const float*)d_in[3];
    const float* bk = (const float*)d_in[4];
    const float* Wv = (const float*)d_in[5];
    const float* bv = (const float*)d_in[6];
    const float* Wo = (const float*)d_in[7];
    const float* bo = (const float*)d_in[8];
    float* out = (float*)d_out;

    float *q, *k, *v, *ctx, *wt;
    cudaGetSymbolAddress((void**)&q,   g_q);
    cudaGetSymbolAddress((void**)&k,   g_k);
    cudaGetSymbolAddress((void**)&v,   g_v);
    cudaGetSymbolAddress((void**)&ctx, g_ctx);
    cudaGetSymbolAddress((void**)&wt,  g_wt);
    float* WqT = wt;
    float* WkT = wt + (size_t)D_MODEL * D_MODEL;
    float* WvT = wt + 2 * (size_t)D_MODEL * D_MODEL;
    float* WoT = wt + 3 * (size_t)D_MODEL * D_MODEL;

    cudaFuncSetAttribute(gemm_mma_kernel, cudaFuncAttributeMaxDynamicSharedMemorySize, GEMM_SMEM_BYTES);
    cudaFuncSetAttribute(attn_mma_kernel, cudaFuncAttributeMaxDynamicSharedMemorySize, ATTN_SMEM_BYTES);

    dim3 tgrid(D_MODEL / 32, D_MODEL / 32);
    transpose_kernel<<<tgrid, 256>>>(Wq, WqT);
    transpose_kernel<<<tgrid, 256>>>(Wk, WkT);
    transpose_kernel<<<tgrid, 256>>>(Wv, WvT);
    transpose_kernel<<<tgrid, 256>>>(Wo, WoT);

    dim3 ggrid(D_MODEL / 128, M_TOTAL / 128);  // (8, 32)
    gemm_mma_kernel<<<ggrid, 256, GEMM_SMEM_BYTES>>>(x, WqT, bq, q);
    gemm_mma_kernel<<<ggrid, 256, GEMM_SMEM_BYTES>>>(x, WkT, bk, k);
    gemm_mma_kernel<<<ggrid, 256, GEMM_SMEM_BYTES>>>(x, WvT, bv, v);

    dim3 agrid(S_LEN / 128, N_HEADS, BATCH);   // (16, 16, 2)
    attn_mma_kernel<<<agrid, 256, ATTN_SMEM_BYTES>>>(q, k, v, ctx);

    gemm_mma_kernel<<<ggrid, 256, GEMM_SMEM_BYTES>>>(ctx, WoT, bo, out);
}

// round 9
// speedup vs baseline: 3.4799x; 1.1365x over previous
#include <cuda_runtime.h>
#include <cstdint>
#include <math.h>

#define D_MODEL 1024
#define S_LEN   2048
#define BATCH   2
#define N_HEADS 16
#define HDIM    64
#define M_TOTAL (BATCH * S_LEN)   // 4096
#define DD ((size_t)D_MODEL * D_MODEL)

// ---------------- scratch (device globals; no allocation allowed) ----------
__device__ float g_xr[(size_t)M_TOTAL * D_MODEL];
__device__ float g_q[(size_t)M_TOTAL * D_MODEL];
__device__ float g_k[(size_t)M_TOTAL * D_MODEL];
__device__ float g_v[(size_t)M_TOTAL * D_MODEL];
__device__ float g_ctx[(size_t)M_TOTAL * D_MODEL];
__device__ float g_wt[4 * DD];   // WqT,WkT,WvT (contiguous [3072,1024]), WoT

// ================= helpers ================================================
__device__ __forceinline__ float to_tf32(float x) {
    float r;
    asm("cvt.rna.tf32.f32 %0, %1;" : "=f"(r) : "f"(x));
    return r;
}
__device__ __forceinline__ uint32_t fau(float x) { return __float_as_uint(x); }
__device__ __forceinline__ uint32_t smem_u32(const void* p) {
    uint32_t a;
    asm("{ .reg .u64 t; cvta.to.shared.u64 t, %1; cvt.u32.u64 %0, t; }" : "=r"(a) : "l"(p));
    return a;
}

#define CP_ASYNC16(sm32, gptr) \
    asm volatile("cp.async.cg.shared.global [%0], [%1], 16;" :: "r"(sm32), "l"(gptr) : "memory")
#define CP_COMMIT() asm volatile("cp.async.commit_group;" ::: "memory")
#define CP_WAIT(n)  asm volatile("cp.async.wait_group %0;" :: "n"(n) : "memory")

// D += A(16x8,row) * B(8x8,col)   tf32 -> f32
__device__ __forceinline__ void mma_tf32(float* d, const uint32_t* a, const uint32_t* b) {
    asm volatile(
        "mma.sync.aligned.m16n8k8.row.col.f32.tf32.tf32.f32 "
        "{%0,%1,%2,%3}, {%4,%5,%6,%7}, {%8,%9}, {%0,%1,%2,%3};"
        : "+f"(d[0]), "+f"(d[1]), "+f"(d[2]), "+f"(d[3])
        : "r"(a[0]), "r"(a[1]), "r"(a[2]), "r"(a[3]), "r"(b[0]), "r"(b[1]));
}

// ================= round x to tf32 ========================================
__global__ __launch_bounds__(256)
void round_x_kernel(const float* __restrict__ in, float* __restrict__ out)
{
    int i = blockIdx.x * 256 + threadIdx.x;
    float4 v = ((const float4*)in)[i];
    v.x = to_tf32(v.x); v.y = to_tf32(v.y); v.z = to_tf32(v.z); v.w = to_tf32(v.w);
    ((float4*)out)[i] = v;
}

// ================= transpose + round: Wt[n*K+k] = rna(W[k*N+n]) ============
__global__ __launch_bounds__(256)
void transpose4_kernel(const float* __restrict__ w0, const float* __restrict__ w1,
                       const float* __restrict__ w2, const float* __restrict__ w3,
                       float* __restrict__ out)
{
    __shared__ float t[32][33];
    const int z = blockIdx.z;
    const float* in = (z == 0) ? w0 : (z == 1) ? w1 : (z == 2) ? w2 : w3;
    float* o = out + (size_t)z * DD;
    const int bx = blockIdx.x * 32, by = blockIdx.y * 32;
    const int x = threadIdx.x & 31;
    const int y0 = (threadIdx.x >> 5) * 4;
    #pragma unroll
    for (int j = 0; j < 4; j++)
        t[y0 + j][x] = in[(size_t)(by + y0 + j) * D_MODEL + bx + x];
    __syncthreads();
    #pragma unroll
    for (int j = 0; j < 4; j++)
        o[(size_t)(bx + y0 + j) * D_MODEL + by + x] = to_tf32(t[x][y0 + j]);
}

// ================= shared GEMM mainloop (cp.async, 3-stage) ================
// CTA 128x128, 8 warps (2m x 4n), warp 64x32, BK=32. A,Bt pre-rounded tf32.
#define GSTR 36
#define GSTAGE (2 * 128 * GSTR)               // floats per stage
#define GEMM_SMEM_BYTES (3 * GSTAGE * 4)      // 110592

__device__ __forceinline__ void gemm_load_chunk(
    const float* __restrict__ A, const float* __restrict__ Bt,
    int m0, int nrow0, int kc, uint32_t stage32, int tid)
{
    #pragma unroll
    for (int p = 0; p < 4; p++) {
        int idx = tid + p * 256;
        int r = idx >> 3, c = (idx & 7) * 4;
        const float* ga = A  + (size_t)(m0 + r)    * D_MODEL + kc * 32 + c;
        const float* gb = Bt + (size_t)(nrow0 + r) * D_MODEL + kc * 32 + c;
        CP_ASYNC16(stage32 + (uint32_t)(r * GSTR + c) * 4, ga);
        CP_ASYNC16(stage32 + (uint32_t)(128 * GSTR + r * GSTR + c) * 4, gb);
    }
}

__device__ __forceinline__ void gemm_mainloop(
    const float* __restrict__ A, const float* __restrict__ Bt,
    int m0, int nrow0, float* sm, float acc[4][4][4])
{
    const int tid = threadIdx.x;
    const int lane = tid & 31;
    const int warp = tid >> 5;
    const int g = lane >> 2;
    const int t = lane & 3;
    const int wm = (warp & 1) * 64;
    const int wn = (warp >> 1) * 32;
    const uint32_t sbase = smem_u32(sm);

    gemm_load_chunk(A, Bt, m0, nrow0, 0, sbase, tid);
    CP_COMMIT();
    gemm_load_chunk(A, Bt, m0, nrow0, 1, sbase + GSTAGE * 4, tid);
    CP_COMMIT();

    int rs = 0, ws = 2;
    for (int i = 0; i < 32; i++) {
        if (i + 2 < 32)
            gemm_load_chunk(A, Bt, m0, nrow0, i + 2, sbase + (uint32_t)ws * GSTAGE * 4, tid);
        CP_COMMIT();
        CP_WAIT(2);
        __syncthreads();

        const float* As = sm + rs * GSTAGE;
        const float* Bs = As + 128 * GSTR;
        #pragma unroll
        for (int ks = 0; ks < 4; ks++) {
            uint32_t bfr[4][2];
            #pragma unroll
            for (int nf = 0; nf < 4; nf++) {
                const float* bp = Bs + (wn + nf * 8 + g) * GSTR + ks * 8 + t;
                bfr[nf][0] = fau(bp[0]);
                bfr[nf][1] = fau(bp[4]);
            }
            #pragma unroll
            for (int mf = 0; mf < 4; mf++) {
                const float* ap = As + (wm + mf * 16 + g) * GSTR + ks * 8 + t;
                uint32_t afr[4];
                afr[0] = fau(ap[0]);
                afr[1] = fau(ap[8 * GSTR]);
                afr[2] = fau(ap[4]);
                afr[3] = fau(ap[8 * GSTR + 4]);
                #pragma unroll
                for (int nf = 0; nf < 4; nf++)
                    mma_tf32(acc[mf][nf], afr, bfr[nf]);
            }
        }
        __syncthreads();
        rs = (rs == 2) ? 0 : rs + 1;
        ws = (ws == 2) ? 0 : ws + 1;
    }
}

#define QSCALE (0.125f * 1.4426950408889634f)

// fused QKV projection: Bt = [WqT;WkT;WvT] as [3072,1024]
__global__ __launch_bounds__(256)
void qkv_gemm_kernel(const float* __restrict__ A, const float* __restrict__ Bt,
                     const float* __restrict__ bq, const float* __restrict__ bk,
                     const float* __restrict__ bv,
                     float* __restrict__ q, float* __restrict__ k, float* __restrict__ v)
{
    extern __shared__ float sm[];
    const int sel = blockIdx.x >> 3;            // 0=q 1=k 2=v
    const int nrow0 = blockIdx.x * 128;         // row in [3072,1024]
    const int n0 = (blockIdx.x & 7) * 128;      // output column
    const int m0 = blockIdx.y * 128;

    float acc[4][4][4];
    #pragma unroll
    for (int mf = 0; mf < 4; mf++)
        #pragma unroll
        for (int nf = 0; nf < 4; nf++)
            #pragma unroll
            for (int r = 0; r < 4; r++) acc[mf][nf][r] = 0.0f;

    gemm_mainloop(A, Bt, m0, nrow0, sm, acc);

    const float* bias = (sel == 0) ? bq : (sel == 1) ? bk : bv;
    float* C = (sel == 0) ? q : (sel == 1) ? k : v;
    const float esc = (sel == 0) ? QSCALE : 1.0f;

    const int lane = threadIdx.x & 31;
    const int warp = threadIdx.x >> 5;
    const int g = lane >> 2;
    const int t = lane & 3;
    const int wm = (warp & 1) * 64;
    const int wn = (warp >> 1) * 32;

    #pragma unroll
    for (int mf = 0; mf < 4; mf++) {
        #pragma unroll
        for (int h = 0; h < 2; h++) {
            const int row = m0 + wm + mf * 16 + g + h * 8;
            float* crow = C + (size_t)row * D_MODEL + n0 + wn;
            #pragma unroll
            for (int nf = 0; nf < 4; nf++) {
                const int col = nf * 8 + 2 * t;
                float2 o;
                o.x = to_tf32((acc[mf][nf][2 * h]     + bias[n0 + wn + col])     * esc);
                o.y = to_tf32((acc[mf][nf][2 * h + 1] + bias[n0 + wn + col + 1]) * esc);
                *(float2*)(crow + col) = o;
            }
        }
    }
}

// output projection: plain fp32 epilogue
__global__ __launch_bounds__(256)
void out_gemm_kernel(const float* __restrict__ A, const float* __restrict__ Bt,
                     const float* __restrict__ bias, float* __restrict__ C)
{
    extern __shared__ float sm[];
    const int nrow0 = blockIdx.x * 128;
    const int n0 = nrow0;
    const int m0 = blockIdx.y * 128;

    float acc[4][4][4];
    #pragma unroll
    for (int mf = 0; mf < 4; mf++)
        #pragma unroll
        for (int nf = 0; nf < 4; nf++)
            #pragma unroll
            for (int r = 0; r < 4; r++) acc[mf][nf][r] = 0.0f;

    gemm_mainloop(A, Bt, m0, nrow0, sm, acc);

    const int lane = threadIdx.x & 31;
    const int warp = threadIdx.x >> 5;
    const int g = lane >> 2;
    const int t = lane & 3;
    const int wm = (warp & 1) * 64;
    const int wn = (warp >> 1) * 32;

    #pragma unroll
    for (int mf = 0; mf < 4; mf++) {
        #pragma unroll
        for (int h = 0; h < 2; h++) {
            const int row = m0 + wm + mf * 16 + g + h * 8;
            float* crow = C + (size_t)row * D_MODEL + n0 + wn;
            #pragma unroll
            for (int nf = 0; nf < 4; nf++) {
                const int col = nf * 8 + 2 * t;
                float2 o;
                o.x = acc[mf][nf][2 * h]     + bias[n0 + wn + col];
                o.y = acc[mf][nf][2 * h + 1] + bias[n0 + wn + col + 1];
                *(float2*)(crow + col) = o;
            }
        }
    }
}

// ================= flash attention: Q in regs, cp.async K/V double-buffer ==
#define AK_STR 68
#define AV_STR 72
#define KSTAGE (64 * AK_STR)
#define VSTAGE (64 * AV_STR)
#define OFF_V (2 * KSTAGE)
#define OFF_P (OFF_V + 2 * VSTAGE)
#define ATTN_SMEM_BYTES ((OFF_P + 128 * AK_STR) * 4)   // 106496

__device__ __forceinline__ void attn_load_kv(
    const float* __restrict__ K, const float* __restrict__ V,
    size_t goff, uint32_t k32, uint32_t v32, int tid)
{
    #pragma unroll
    for (int p = 0; p < 4; p++) {
        int idx = tid + p * 256;
        int r = idx >> 4, c = (idx & 15) * 4;
        size_t go = goff + (size_t)r * D_MODEL + c;
        CP_ASYNC16(k32 + (uint32_t)(r * AK_STR + c) * 4, K + go);
        CP_ASYNC16(v32 + (uint32_t)(r * AV_STR + c) * 4, V + go);
    }
}

__global__ __launch_bounds__(256, 2)
void attn_mma_kernel(const float* __restrict__ Q, const float* __restrict__ K,
                     const float* __restrict__ V, float* __restrict__ Out)
{
    extern __shared__ float sm[];
    float* Ps = sm + OFF_P;
    const uint32_t sbase = smem_u32(sm);

    const int tid = threadIdx.x;
    const int lane = tid & 31;
    const int warp = tid >> 5;
    const int g = lane >> 2;
    const int t = lane & 3;
    const int q0 = blockIdx.x * 128;
    const size_t hoff = (size_t)blockIdx.y * HDIM;
    const size_t boff = (size_t)blockIdx.z * S_LEN * D_MODEL;

    // Q fragments in registers (q pre-scaled by QSCALE and tf32-rounded)
    uint32_t qa[8][4];
    {
        const float* q0p = Q + boff + (size_t)(q0 + warp * 16 + g) * D_MODEL + hoff;
        const float* q8p = q0p + 8 * D_MODEL;
        #pragma unroll
        for (int ks = 0; ks < 8; ks++) {
            qa[ks][0] = fau(q0p[ks * 8 + t]);
            qa[ks][1] = fau(q8p[ks * 8 + t]);
            qa[ks][2] = fau(q0p[ks * 8 + t + 4]);
            qa[ks][3] = fau(q8p[ks * 8 + t + 4]);
        }
    }

    float o[8][4];
    #pragma unroll
    for (int nf = 0; nf < 8; nf++)
        #pragma unroll
        for (int r = 0; r < 4; r++) o[nf][r] = 0.0f;
    float mrun[2] = {-1e30f, -1e30f};
    float lrun[2] = {0.0f, 0.0f};

    // prologue: stage 0 = kt 0
    attn_load_kv(K, V, boff + hoff, sbase, sbase + OFF_V * 4, tid);
    CP_COMMIT();

    for (int kt = 0; kt < 32; kt++) {
        const int s = kt & 1;
        if (kt + 1 < 32)
            attn_load_kv(K, V, boff + (size_t)(kt + 1) * 64 * D_MODEL + hoff,
                         sbase + (uint32_t)((s ^ 1) * KSTAGE) * 4,
                         sbase + (uint32_t)(OFF_V + (s ^ 1) * VSTAGE) * 4, tid);
        CP_COMMIT();
        CP_WAIT(1);
        __syncthreads();

        const float* Ks = sm + s * KSTAGE;
        const float* Vs = sm + OFF_V + s * VSTAGE;

        // S = Q * K^T
        float sc[8][4];
        #pragma unroll
        for (int nf = 0; nf < 8; nf++)
            #pragma unroll
            for (int r = 0; r < 4; r++) sc[nf][r] = 0.0f;
        #pragma unroll
        for (int ks = 0; ks < 8; ks++) {
            #pragma unroll
            for (int nf = 0; nf < 8; nf++) {
                const float* bp = Ks + (nf * 8 + g) * AK_STR + ks * 8 + t;
                uint32_t b[2] = {fau(bp[0]), fau(bp[4])};
                mma_tf32(sc[nf], qa[ks], b);
            }
        }

        // online softmax per row-half
        #pragma unroll
        for (int h = 0; h < 2; h++) {
            float mx = mrun[h];
            #pragma unroll
            for (int nf = 0; nf < 8; nf++)
                mx = fmaxf(mx, fmaxf(sc[nf][2 * h], sc[nf][2 * h + 1]));
            mx = fmaxf(mx, __shfl_xor_sync(0xffffffffu, mx, 1));
            mx = fmaxf(mx, __shfl_xor_sync(0xffffffffu, mx, 2));
            float corr = exp2f(mrun[h] - mx);
            float rs = 0.0f;
            float* prow = Ps + (warp * 16 + g + 8 * h) * AK_STR + 2 * t;
            #pragma unroll
            for (int nf = 0; nf < 8; nf++) {
                float e0 = exp2f(sc[nf][2 * h] - mx);
                float e1 = exp2f(sc[nf][2 * h + 1] - mx);
                rs += e0 + e1;
                *(float2*)(prow + nf * 8) = make_float2(to_tf32(e0), to_tf32(e1));
            }
            rs += __shfl_xor_sync(0xffffffffu, rs, 1);
            rs += __shfl_xor_sync(0xffffffffu, rs, 2);
            lrun[h] = lrun[h] * corr + rs;
            mrun[h] = mx;
            #pragma unroll
            for (int nf = 0; nf < 8; nf++) {
                o[nf][2 * h]     *= corr;
                o[nf][2 * h + 1] *= corr;
            }
        }
        __syncwarp();   // own-warp P stores visible

        // O += P * V
        #pragma unroll
        for (int ks = 0; ks < 8; ks++) {
            const float* ap = Ps + (warp * 16 + g) * AK_STR + ks * 8 + t;
            uint32_t a[4];
            a[0] = fau(ap[0]);
            a[1] = fau(ap[8 * AK_STR]);
            a[2] = fau(ap[4]);
            a[3] = fau(ap[8 * AK_STR + 4]);
            #pragma unroll
            for (int nf = 0; nf < 8; nf++) {
                const float* bp = Vs + (ks * 8 + t) * AV_STR + nf * 8 + g;
                uint32_t b[2] = {fau(bp[0]), fau(bp[4 * AV_STR])};
                mma_tf32(o[nf], a, b);
            }
        }
        __syncthreads();   // stage s fully read before next prefetch overwrites
    }

    // epilogue: normalize, round to tf32 for the O-projection, write ctx
    #pragma unroll
    for (int h = 0; h < 2; h++) {
        const int row = q0 + warp * 16 + g + 8 * h;
        const float inv = 1.0f / lrun[h];
        float* op = Out + boff + (size_t)row * D_MODEL + hoff;
        #pragma unroll
        for (int nf = 0; nf < 8; nf++) {
            float2 v = make_float2(to_tf32(o[nf][2 * h] * inv),
                                   to_tf32(o[nf][2 * h + 1] * inv));
            *(float2*)(op + nf * 8 + 2 * t) = v;
        }
    }
}

// ---------------- launch -------------------------------------------------
extern "C" void kernel_launch(void* const* d_in, const int* in_sizes, int n_in,
                              void* d_out, int out_size)
{
    const float* x  = (const float*)d_in[0];
    const float* Wq = (const float*)d_in[1];
    const float* bq = (const float*)d_in[2];
    const float* Wk = (const float*)d_in[3];
    const float* bk = (const float*)d_in[4];
    const float* Wv = (const float*)d_in[5];
    const float* bv = (const float*)d_in[6];
    const float* Wo = (const float*)d_in[7];
    const float* bo = (const float*)d_in[8];
    float* out = (float*)d_out;

    float *xr, *q, *k, *v, *ctx, *wt;
    cudaGetSymbolAddress((void**)&xr,  g_xr);
    cudaGetSymbolAddress((void**)&q,   g_q);
    cudaGetSymbolAddress((void**)&k,   g_k);
    cudaGetSymbolAddress((void**)&v,   g_v);
    cudaGetSymbolAddress((void**)&ctx, g_ctx);
    cudaGetSymbolAddress((void**)&wt,  g_wt);

    cudaFuncSetAttribute(qkv_gemm_kernel, cudaFuncAttributeMaxDynamicSharedMemorySize, GEMM_SMEM_BYTES);
    cudaFuncSetAttribute(out_gemm_kernel, cudaFuncAttributeMaxDynamicSharedMemorySize, GEMM_SMEM_BYTES);
    cudaFuncSetAttribute(attn_mma_kernel, cudaFuncAttributeMaxDynamicSharedMemorySize, ATTN_SMEM_BYTES);

    round_x_kernel<<<(M_TOTAL * D_MODEL) / (256 * 4), 256>>>(x, xr);

    dim3 tgrid(D_MODEL / 32, D_MODEL / 32, 4);
    transpose4_kernel<<<tgrid, 256>>>(Wq, Wk, Wv, Wo, wt);

    dim3 qkvgrid(3 * D_MODEL / 128, M_TOTAL / 128);  // (24, 32)
    qkv_gemm_kernel<<<qkvgrid, 256, GEMM_SMEM_BYTES>>>(xr, wt, bq, bk, bv, q, k, v);

    dim3 agrid(S_LEN / 128, N_HEADS, BATCH);         // (16, 16, 2)
    attn_mma_kernel<<<agrid, 256, ATTN_SMEM_BYTES>>>(q, k, v, ctx);

    dim3 ogrid(D_MODEL / 128, M_TOTAL / 128);        // (8, 32)
    out_gemm_kernel<<<ogrid, 256, GEMM_SMEM_BYTES>>>(ctx, wt + 3 * DD, bo, out);
}